// round 5
// baseline (speedup 1.0000x reference)
#include <cuda_runtime.h>
#include <cuda_bf16.h>

// Problem constants
#define BB   4
#define HH   160
#define WW   288
#define HO   80
#define WO   144
#define HWO  (HO*WO)     // 11520
#define DMAX 24
#define EPSV 1e-5f

// Scratch (no allocation allowed -> __device__ globals)
__device__ float d_plg[3*BB*144*HWO];  // gwc partial logits, 3 oc-splits
__device__ float d_plc[BB*112*HWO];    // cat logits (tap-stride padded to 112)
__device__ float d_g8[BB*96*HWO];      // gwc downsampled features
__device__ float d_c8[BB*12*HWO];      // cat downsampled features

// ---- packed f32x2 helpers (sm_100+) ---------------------------------------
typedef unsigned long long ull;
__device__ __forceinline__ ull pack2(float v) {
    ull r; asm("mov.b64 %0, {%1, %1};" : "=l"(r) : "f"(v)); return r;
}
__device__ __forceinline__ ull pack2d(float lo, float hi) {
    ull r; asm("mov.b64 %0, {%1, %2};" : "=l"(r) : "f"(lo), "f"(hi)); return r;
}
__device__ __forceinline__ void ffma2(ull& acc, ull a, ull b) {
    asm("fma.rn.f32x2 %0, %1, %2, %0;" : "+l"(acc) : "l"(a), "l"(b));
}
__device__ __forceinline__ void unpack2(ull v, float& lo, float& hi) {
    asm("mov.b64 {%0, %1}, %2;" : "=f"(lo), "=f"(hi) : "l"(v));
}

// ---------------------------------------------------------------------------
// Kernel 1: 3x3 stride-2 conv + BN + LeakyReLU fused with the 1x1 mask-logit
// GEMM. Each block: 8x16 output pixels x OCB output channels. Main loop is
// the software-pipelined conv; epilogue stages y (post BN/lrelu) into smem
// and computes this oc-slice's contribution to all NTAP mask logits, written
// to a per-split logits buffer (summed later in mask_agg). y itself is never
// materialized in global memory.
// ---------------------------------------------------------------------------
template<int CIN, int COUT, int OCB, int NTAP, int NTAP_P>
__global__ __launch_bounds__(256, 2)
void conv1_fused(const float* __restrict__ x, const float* __restrict__ w,
                 const float* __restrict__ bng, const float* __restrict__ bnb,
                 const float* __restrict__ bnm, const float* __restrict__ bnv,
                 const float* __restrict__ w2, float* __restrict__ plg)
{
    constexpr int NOC  = (COUT + OCB - 1) / OCB;
    constexpr int OCT  = OCB / 8;                 // oc per thread
    constexpr int NP   = OCT / 2;                 // oc pairs per thread
    constexpr int NCH  = CIN / 4;                 // ic chunks
    constexpr int INEL = 4 * 17 * 36;             // padded patch (stride 36)
    constexpr int NIN  = (INEL + 255) / 256;      // 10
    constexpr int WEL  = 36 * OCB;
    constexpr int NWT  = (WEL + 255) / 256;
    constexpr int YSTR = OCB + 2;                 // y_s row stride (even)
    constexpr int TSTR = NTAP_P + 2;              // w2t_s row stride (even)
    constexpr int NTC  = NTAP_P / 8;              // tap chunks of 8

    extern __shared__ __align__(16) float smem[];
    float* in_s = smem;                 // INEL
    float* w_s  = smem + INEL;          // WEL

    const int bz      = blockIdx.z;
    const int b       = bz / NOC;
    const int sblk    = bz % NOC;                 // oc split index
    const int oc_base = sblk * OCB;
    const int oh0 = blockIdx.y * 8;
    const int ow0 = blockIdx.x * 16;
    const int ih0 = oh0 * 2 - 1;
    const int iw0 = ow0 * 2 - 1;

    const int tid = threadIdx.x;
    const int og  = tid >> 5;
    const int pq  = tid & 31;
    const int ph  = pq >> 2;
    const int pw0 = (pq & 3) * 4;

    // ---- per-thread load descriptors (reused every chunk) -----------------
    int  in_goff[NIN];  bool in_st[NIN], in_ok[NIN];
    #pragma unroll
    for (int j = 0; j < NIN; ++j) {
        int idx = tid + j * 256;
        in_st[j] = (idx < INEL);
        int ic = idx / 612, rem = idx % 612;
        int ih = rem / 36,  iw  = rem % 36;
        int gh = ih0 + ih,  gw  = iw0 + iw;
        in_ok[j]   = in_st[j] && iw < 33 &&
                     (unsigned)gh < (unsigned)HH && (unsigned)gw < (unsigned)WW;
        in_goff[j] = in_ok[j] ? (ic * (HH * WW) + gh * WW + gw) : 0;
    }
    int  wt_goff[NWT];  bool wt_st[NWT], wt_ok[NWT];
    #pragma unroll
    for (int j = 0; j < NWT; ++j) {
        int idx = tid + j * 256;
        wt_st[j] = (idx < WEL);
        int oc_l = idx % OCB;
        int r    = idx / OCB;                     // ic*9 + tap
        int oc_g = oc_base + oc_l;
        wt_ok[j]   = wt_st[j] && (oc_g < COUT);
        wt_goff[j] = wt_ok[j] ? (oc_g * (CIN * 9) + r) : 0;
    }

    const float* xb = x + (size_t)b * CIN * HH * WW;

    ull acc2[NP][4];
    #pragma unroll
    for (int k = 0; k < NP; ++k)
        #pragma unroll
        for (int j = 0; j < 4; ++j) acc2[k][j] = 0ull;

    float rin[NIN], rw[NWT];
    #pragma unroll
    for (int j = 0; j < NIN; ++j)
        rin[j] = in_ok[j] ? __ldg(xb + in_goff[j]) : 0.f;
    #pragma unroll
    for (int j = 0; j < NWT; ++j)
        rw[j] = wt_ok[j] ? __ldg(w + wt_goff[j]) : 0.f;

    for (int c = 0; c < NCH; ++c) {
        __syncthreads();
        #pragma unroll
        for (int j = 0; j < NIN; ++j)
            if (in_st[j]) in_s[tid + j * 256] = rin[j];
        #pragma unroll
        for (int j = 0; j < NWT; ++j)
            if (wt_st[j]) w_s[tid + j * 256] = rw[j];
        __syncthreads();

        if (c + 1 < NCH) {
            const float* xn = xb + (size_t)(c + 1) * 4 * HH * WW;
            const float* wn = w + (size_t)(c + 1) * 4 * 9;
            #pragma unroll
            for (int j = 0; j < NIN; ++j)
                rin[j] = in_ok[j] ? __ldg(xn + in_goff[j]) : 0.f;
            #pragma unroll
            for (int j = 0; j < NWT; ++j)
                rw[j] = wt_ok[j] ? __ldg(wn + wt_goff[j]) : 0.f;
        }

        #pragma unroll
        for (int ic = 0; ic < 4; ++ic) {
            #pragma unroll
            for (int kh = 0; kh < 3; ++kh) {
                const float* ip = &in_s[ic * 612 + (ph * 2 + kh) * 36 + pw0 * 2];
                float4 va = *(const float4*)ip;
                float4 vb = *(const float4*)(ip + 4);
                float  v8 = ip[8];
                float iv[9] = {va.x, va.y, va.z, va.w, vb.x, vb.y, vb.z, vb.w, v8};
                #pragma unroll
                for (int kw = 0; kw < 3; ++kw) {
                    ull ipk[4];
                    #pragma unroll
                    for (int j = 0; j < 4; ++j) ipk[j] = pack2(iv[2 * j + kw]);
                    const ull* wp = (const ull*)
                        &w_s[(ic * 9 + kh * 3 + kw) * OCB + og * OCT];
                    #pragma unroll
                    for (int k = 0; k < NP; ++k) {
                        ull wv = wp[k];
                        #pragma unroll
                        for (int j = 0; j < 4; ++j) ffma2(acc2[k][j], wv, ipk[j]);
                    }
                }
            }
        }
    }

    // ---- epilogue: BN + lrelu -> y_s, w2 tile -> w2t_s, logits GEMM -------
    __syncthreads();                 // main-loop smem reads complete
    float* y_s   = smem;             // 128 x YSTR
    float* w2t_s = smem + 128 * YSTR; // OCB x TSTR

    #pragma unroll
    for (int k = 0; k < NP; ++k) {
        int oc0 = oc_base + og * OCT + 2 * k;
        float sc0 = 0.f, sh0 = 0.f, sc1 = 0.f, sh1 = 0.f;
        if (oc0 < COUT) {
            sc0 = bng[oc0] * rsqrtf(bnv[oc0] + EPSV);
            sh0 = bnb[oc0] - bnm[oc0] * sc0;
        }
        if (oc0 + 1 < COUT) {
            sc1 = bng[oc0 + 1] * rsqrtf(bnv[oc0 + 1] + EPSV);
            sh1 = bnb[oc0 + 1] - bnm[oc0 + 1] * sc1;
        }
        #pragma unroll
        for (int j = 0; j < 4; ++j) {
            float lo, hi;
            unpack2(acc2[k][j], lo, hi);
            lo = lo * sc0 + sh0;  lo = (lo >= 0.f) ? lo : 0.1f * lo;
            hi = hi * sc1 + sh1;  hi = (hi >= 0.f) ? hi : 0.1f * hi;
            int px = ph * 16 + pw0 + j;
            *(ull*)&y_s[px * YSTR + og * OCT + 2 * k] = pack2d(lo, hi);
        }
    }
    for (int idx = tid; idx < OCB * NTAP_P; idx += 256) {
        int oc_l = idx / NTAP_P, t = idx % NTAP_P;
        int oc_g = oc_base + oc_l;
        float v = 0.f;
        if (t < NTAP && oc_g < COUT) v = __ldg(w2 + (size_t)t * COUT + oc_g);
        w2t_s[oc_l * TSTR + t] = v;
    }
    __syncthreads();

    for (int tile = tid; tile < 32 * NTC; tile += 256) {
        int pc = tile & 31, tc = tile >> 5;
        ull a2[4][4];
        #pragma unroll
        for (int j = 0; j < 4; ++j)
            #pragma unroll
            for (int tp = 0; tp < 4; ++tp) a2[j][tp] = 0ull;

        const float* yb = &y_s[(pc * 4) * YSTR];
        const float* wb = &w2t_s[tc * 8];
        #pragma unroll 4
        for (int oc = 0; oc < OCB; ++oc) {
            ull wv[4];
            #pragma unroll
            for (int tp = 0; tp < 4; ++tp)
                wv[tp] = *(const ull*)&wb[oc * TSTR + 2 * tp];
            #pragma unroll
            for (int j = 0; j < 4; ++j) {
                ull yk = pack2(yb[j * YSTR + oc]);
                #pragma unroll
                for (int tp = 0; tp < 4; ++tp) ffma2(a2[j][tp], wv[tp], yk);
            }
        }

        int pcb  = pc * 4;
        int pixg = (oh0 + (pcb >> 4)) * WO + ow0 + (pcb & 15);
        size_t base = ((size_t)(sblk * BB + b)) * NTAP_P;
        #pragma unroll
        for (int tp = 0; tp < 4; ++tp) {
            float l0, h0, l1, h1, l2, h2, l3, h3;
            unpack2(a2[0][tp], l0, h0); unpack2(a2[1][tp], l1, h1);
            unpack2(a2[2][tp], l2, h2); unpack2(a2[3][tp], l3, h3);
            int t0 = tc * 8 + 2 * tp;
            if (NTAP == NTAP_P || t0 < NTAP) {
                float4 v = make_float4(l0, l1, l2, l3);
                *(float4*)&plg[(base + t0) * HWO + pixg] = v;
            }
            if (NTAP == NTAP_P || t0 + 1 < NTAP) {
                float4 v = make_float4(h0, h1, h2, h3);
                *(float4*)&plg[(base + t0 + 1) * HWO + pixg] = v;
            }
        }
    }
}

// ---------------------------------------------------------------------------
// Kernel 2: sum partial logits -> softmax over 9 taps -> weighted unfold
// aggregation. One thread = one pixel, one block = one group.
// ---------------------------------------------------------------------------
template<int NG, int CPG, int NSPLIT, int NTAP_P>
__global__ __launch_bounds__(128)
void mask_agg(const float* __restrict__ plg, const float* __restrict__ x,
              float* __restrict__ out)
{
    constexpr int XC = NG * CPG;
    const int pix = blockIdx.x * 128 + threadIdx.x;
    const int g   = blockIdx.y;
    const int b   = pix / HWO;
    const int rem = pix % HWO;
    const int oh  = rem / WO, ow = rem % WO;

    float acc[9];
    #pragma unroll
    for (int t = 0; t < 9; ++t) acc[t] = 0.f;
    #pragma unroll
    for (int s = 0; s < NSPLIT; ++s) {
        const float* p = plg + (((size_t)(s * BB + b)) * NTAP_P + g * 9) * HWO + rem;
        #pragma unroll
        for (int t = 0; t < 9; ++t) acc[t] += __ldg(p + (size_t)t * HWO);
    }

    float m = acc[0];
    #pragma unroll
    for (int t = 1; t < 9; ++t) m = fmaxf(m, acc[t]);
    float e[9], s = 0.f;
    #pragma unroll
    for (int t = 0; t < 9; ++t) { e[t] = __expf(acc[t] - m); s += e[t]; }
    float inv = 1.f / s;
    #pragma unroll
    for (int t = 0; t < 9; ++t) e[t] *= inv;

    #pragma unroll
    for (int i = 0; i < CPG; ++i) {
        int c = i * NG + g;
        const float* xc = x + ((size_t)(b * XC + c)) * HH * WW;
        float sum = 0.f;
        #pragma unroll
        for (int kh = 0; kh < 3; ++kh) {
            int ih = 2 * oh + kh - 1;
            #pragma unroll
            for (int kw = 0; kw < 3; ++kw) {
                int iw = 2 * ow + kw - 1;
                float xv = 0.f;
                if ((unsigned)ih < (unsigned)HH && (unsigned)iw < (unsigned)WW)
                    xv = __ldg(xc + ih * WW + iw);
                sum += e[kh * 3 + kw] * xv;
            }
        }
        out[((size_t)(b * XC + c)) * HWO + rem] = sum;
    }
}

// ---------------------------------------------------------------------------
// Kernel 3: group-wise correlation volume.
// ---------------------------------------------------------------------------
__global__ __launch_bounds__(160)
void gwc_vol(const float* __restrict__ g8, float* __restrict__ out)
{
    const int h = blockIdx.x;
    const int g = blockIdx.y;
    const int b = blockIdx.z;

    __shared__ float ls[12][WO];
    __shared__ float rs[12][WO];

    for (int idx = threadIdx.x; idx < 2 * 12 * WO; idx += 160) {
        int half = idx / (12 * WO);
        int rem  = idx % (12 * WO);
        int c = rem / WO, w = rem % WO;
        int bb = half == 0 ? b : b + 2;
        float v = g8[(((size_t)bb * 96 + g * 12 + c) * HO + h) * WO + w];
        if (half == 0) ls[c][w] = v; else rs[c][w] = v;
    }
    __syncthreads();

    const int w = threadIdx.x;
    if (w < WO) {
        float lr[12];
        #pragma unroll
        for (int c = 0; c < 12; ++c) lr[c] = ls[c][w];
        for (int d = 0; d < DMAX; ++d) {
            float s = 0.f;
            if (w >= d) {
                #pragma unroll
                for (int c = 0; c < 12; ++c) s += lr[c] * rs[c][w - d];
                s *= (1.f / 12.f);
            }
            out[((((size_t)b * 32 + g) * DMAX + d) * HO + h) * WO + w] = s;
        }
    }
}

// ---------------------------------------------------------------------------
// Kernel 4: concat volume — pure gather into out channels [8, 32).
// ---------------------------------------------------------------------------
__global__ __launch_bounds__(256)
void cat_vol(const float* __restrict__ c8, float* __restrict__ out)
{
    int idx = blockIdx.x * 256 + threadIdx.x;
    int w = idx % WO; int t = idx / WO;
    int h = t % HO; t /= HO;
    int d = t % DMAX; t /= DMAX;
    int ch = t % 24; int b = t / 24;

    float v = 0.f;
    if (w >= d) {
        v = (ch < 12)
          ? c8[(((size_t)b * 12 + ch) * HO + h) * WO + w]
          : c8[((((size_t)b + 2) * 12 + (ch - 12)) * HO + h) * WO + (w - d)];
    }
    out[((((size_t)b * 32 + 8 + ch) * DMAX + d) * HO + h) * WO + w] = v;
}

// ---------------------------------------------------------------------------
extern "C" void kernel_launch(void* const* d_in, const int* in_sizes, int n_in,
                              void* d_out, int out_size)
{
    const float* gwc_x   = (const float*)d_in[0];
    const float* cat_x   = (const float*)d_in[1];
    const float* g_w1    = (const float*)d_in[2];
    const float* g_bng   = (const float*)d_in[3];
    const float* g_bnb   = (const float*)d_in[4];
    const float* g_bnm   = (const float*)d_in[5];
    const float* g_bnv   = (const float*)d_in[6];
    const float* g_w2    = (const float*)d_in[7];
    const float* c_w1    = (const float*)d_in[8];
    const float* c_bng   = (const float*)d_in[9];
    const float* c_bnb   = (const float*)d_in[10];
    const float* c_bnm   = (const float*)d_in[11];
    const float* c_bnv   = (const float*)d_in[12];
    const float* c_w2    = (const float*)d_in[13];
    float* out = (float*)d_out;

    float *plg, *plc, *g8, *c8;
    cudaGetSymbolAddress((void**)&plg, d_plg);
    cudaGetSymbolAddress((void**)&plc, d_plc);
    cudaGetSymbolAddress((void**)&g8, d_g8);
    cudaGetSymbolAddress((void**)&c8, d_c8);

    // smem: max(pipeline, epilogue) bytes
    constexpr int SM_G = (128 * 66 + 64 * 146) * 4;   // 71168
    constexpr int SM_C = (128 * 34 + 32 * 114) * 4;   // 32000

    static bool attr_done = false;
    if (!attr_done) {
        cudaFuncSetAttribute(conv1_fused<96, 192, 64, 144, 144>,
                             cudaFuncAttributeMaxDynamicSharedMemorySize, SM_G);
        cudaFuncSetAttribute(conv1_fused<12, 24, 32, 108, 112>,
                             cudaFuncAttributeMaxDynamicSharedMemorySize, SM_C);
        attr_done = true;
    }

    // conv1 + BN + LeakyReLU fused with mask-logit GEMM
    conv1_fused<96, 192, 64, 144, 144><<<dim3(WO/16, HO/8, BB * 3), 256, SM_G>>>(
        gwc_x, g_w1, g_bng, g_bnb, g_bnm, g_bnv, g_w2, plg);
    conv1_fused<12, 24, 32, 108, 112><<<dim3(WO/16, HO/8, BB * 1), 256, SM_C>>>(
        cat_x, c_w1, c_bng, c_bnb, c_bnm, c_bnv, c_w2, plc);

    // logits sum + softmax + unfold aggregation
    mask_agg<16, 6, 3, 144><<<dim3(BB * HWO / 128, 16), 128>>>(plg, gwc_x, g8);
    mask_agg<12, 1, 1, 112><<<dim3(BB * HWO / 128, 12), 128>>>(plc, cat_x, c8);

    // cost volumes
    gwc_vol<<<dim3(HO, 8, 2), 160>>>(g8, out);
    cat_vol<<<(2 * 24 * DMAX * HO * WO) / 256, 256>>>(c8, out);
}